// round 1
// baseline (speedup 1.0000x reference)
#include <cuda_runtime.h>
#include <stdint.h>

// Problem constants (from reference setup_inputs)
#define B_DIM 32
#define T_DIM 512
#define D_DIM 384
#define DUR_MAX 8
#define T_OUT (T_DIM * DUR_MAX)   // 4096
#define D4 (D_DIM / 4)             // 96 float4 per frame

// Scratch (allocation-free rule: __device__ globals)
__device__ int g_total;
__device__ int g_idx[B_DIM * T_OUT];   // frame -> phoneme index, -1 = pad

// ---------------------------------------------------------------------------
// Kernel 1: global sum of all durations (edge case: all-zero -> durations = 1)
// ---------------------------------------------------------------------------
__global__ void total_kernel(const int* __restrict__ dur, int n) {
    __shared__ int sdata[256];
    int sum = 0;
    for (int i = threadIdx.x; i < n; i += 256) sum += dur[i];
    // warp reduce
    #pragma unroll
    for (int off = 16; off > 0; off >>= 1)
        sum += __shfl_down_sync(0xffffffffu, sum, off);
    if ((threadIdx.x & 31) == 0) sdata[threadIdx.x >> 5] = sum;
    __syncthreads();
    if (threadIdx.x < 8) {
        int s = sdata[threadIdx.x];
        #pragma unroll
        for (int off = 4; off > 0; off >>= 1)
            s += __shfl_down_sync(0xffu, s, off);
        if (threadIdx.x == 0) g_total = s;
    }
}

// ---------------------------------------------------------------------------
// Kernel 2: per-row inclusive scan + scatter frame->phoneme map
// one block per batch row, 512 threads (= T_DIM)
// ---------------------------------------------------------------------------
__global__ void scan_scatter_kernel(const int* __restrict__ dur) {
    __shared__ int s_cum[T_DIM];
    const int b = blockIdx.x;
    const int j = threadIdx.x;

    int d = dur[b * T_DIM + j];
    if (g_total == 0) d = 1;   // torch edge case: all-zero durations -> ones

    s_cum[j] = d;
    __syncthreads();
    // Hillis-Steele inclusive scan over 512 elements
    #pragma unroll
    for (int off = 1; off < T_DIM; off <<= 1) {
        int v = (j >= off) ? s_cum[j - off] : 0;
        __syncthreads();
        s_cum[j] += v;
        __syncthreads();
    }

    const int end   = s_cum[j];
    const int start = end - d;
    int* __restrict__ idx = g_idx + b * T_OUT;
    for (int k = start; k < end; ++k) idx[k] = j;

    __syncthreads();
    const int total = s_cum[T_DIM - 1];
    for (int t = total + j; t < T_OUT; t += T_DIM) idx[t] = -1;
}

// ---------------------------------------------------------------------------
// Kernel 3: the heavy gather. block = (96, 4): 4 frames per block,
// 96 lanes move one frame (384 floats) as float4.
// ---------------------------------------------------------------------------
__global__ void __launch_bounds__(D4 * 4) gather_kernel(
    const float4* __restrict__ xs, float4* __restrict__ out)
{
    const int frame = blockIdx.x * 4 + threadIdx.y;       // 0 .. B*T_OUT-1
    const int lane  = threadIdx.x;                        // 0 .. 95
    const int id    = __ldg(&g_idx[frame]);               // broadcast within frame
    const int b     = frame >> 12;                        // / T_OUT (4096)

    float4 v;
    if (id >= 0) {
        v = __ldg(&xs[(b * T_DIM + id) * D4 + lane]);
    } else {
        v = make_float4(0.f, 0.f, 0.f, 0.f);
    }
    out[(size_t)frame * D4 + lane] = v;
}

// ---------------------------------------------------------------------------
extern "C" void kernel_launch(void* const* d_in, const int* in_sizes, int n_in,
                              void* d_out, int out_size) {
    const float* xs  = (const float*)d_in[0];   // [B, T, D] f32
    const int*   dur = (const int*)d_in[1];     // [B, T] i32
    float* out = (float*)d_out;                 // [B, T_OUT, D] f32

    (void)in_sizes; (void)n_in; (void)out_size;

    total_kernel<<<1, 256>>>(dur, B_DIM * T_DIM);
    scan_scatter_kernel<<<B_DIM, T_DIM>>>(dur);

    dim3 blk(D4, 4);                            // 384 threads
    dim3 grd((B_DIM * T_OUT) / 4);              // 32768 blocks
    gather_kernel<<<grd, blk>>>((const float4*)xs, (float4*)out);
}

// round 2
// speedup vs baseline: 1.4371x; 1.4371x over previous
#include <cuda_runtime.h>
#include <stdint.h>

// Problem constants (from reference setup_inputs)
#define B_DIM 32
#define T_DIM 512
#define D_DIM 384
#define DUR_MAX 8
#define T_OUT (T_DIM * DUR_MAX)   // 4096
#define D4 (D_DIM / 4)            // 96 float4 per frame

// Scratch (allocation-free rule: __device__ globals)
__device__ int g_total;
__device__ int g_idx[B_DIM * T_OUT];   // frame -> phoneme index, -1 = pad

// ---------------------------------------------------------------------------
// Fused prep kernel: grid = 33 blocks.
//   blocks 0..31 : per-row inclusive scan (shfl-based) + scatter idx map
//   block  32    : global duration sum -> g_total (edge case handled in gather)
// ---------------------------------------------------------------------------
__global__ void __launch_bounds__(T_DIM) prep_kernel(const int* __restrict__ dur) {
    const int b = blockIdx.x;
    const int j = threadIdx.x;

    if (b == B_DIM) {
        // ---- global total over all 16384 durations, int4 vectorized ----
        const int4* d4 = (const int4*)dur;          // 4096 int4
        int sum = 0;
        #pragma unroll
        for (int i = 0; i < 8; ++i) {
            int4 v = d4[j + i * T_DIM];
            sum += v.x + v.y + v.z + v.w;
        }
        #pragma unroll
        for (int off = 16; off > 0; off >>= 1)
            sum += __shfl_down_sync(0xffffffffu, sum, off);
        __shared__ int sw[16];
        if ((j & 31) == 0) sw[j >> 5] = sum;
        __syncthreads();
        if (j < 16) {
            int s = sw[j];
            #pragma unroll
            for (int off = 8; off > 0; off >>= 1)
                s += __shfl_down_sync(0xffffu, s, off);
            if (j == 0) g_total = s;
        }
        return;
    }

    // ---- per-row inclusive scan of durations (no edge-case adjustment) ----
    const int lane = j & 31;
    const int wid  = j >> 5;                        // 16 warps
    int d = dur[b * T_DIM + j];

    int x = d;
    #pragma unroll
    for (int off = 1; off < 32; off <<= 1) {
        int v = __shfl_up_sync(0xffffffffu, x, off);
        if (lane >= off) x += v;
    }

    __shared__ int warpsum[16];
    __shared__ int warppre[16];
    if (lane == 31) warpsum[wid] = x;
    __syncthreads();
    if (j < 16) {
        int v = warpsum[j];
        int p = v;
        #pragma unroll
        for (int off = 1; off < 16; off <<= 1) {
            int t = __shfl_up_sync(0xffffu, p, off);
            if (j >= off) p += t;
        }
        warppre[j] = p - v;                         // exclusive prefix of warp sums
    }
    __syncthreads();

    const int end   = x + warppre[wid];             // inclusive cumsum
    const int start = end - d;
    int* __restrict__ idx = g_idx + b * T_OUT;
    for (int k = start; k < end; ++k) idx[k] = j;

    __shared__ int s_total;
    if (j == T_DIM - 1) s_total = end;
    __syncthreads();
    for (int t = s_total + j; t < T_OUT; t += T_DIM) idx[t] = -1;
}

// ---------------------------------------------------------------------------
// Gather: block (96,4), 16 frames per block, 4 independent gathers per thread.
// ---------------------------------------------------------------------------
__global__ void __launch_bounds__(D4 * 4) gather_kernel(
    const float4* __restrict__ xs, float4* __restrict__ out)
{
    const int base = blockIdx.x * 16;               // first frame of block
    const int lane = threadIdx.x;                   // 0..95
    const int y    = threadIdx.y;                   // 0..3
    const int tot  = g_total;                       // uniform; edge case only

    int id[4];
    #pragma unroll
    for (int k = 0; k < 4; ++k)
        id[k] = __ldg(&g_idx[base + y + 4 * k]);

    #pragma unroll
    for (int k = 0; k < 4; ++k) {
        const int frame = base + y + 4 * k;
        int i = id[k];
        if (i < 0 && tot == 0) {
            // torch edge case: all durations zero -> treated as ones
            const int t = frame & (T_OUT - 1);
            if (t < T_DIM) i = t;
        }
        float4 v = make_float4(0.f, 0.f, 0.f, 0.f);
        if (i >= 0) {
            const int bb = frame >> 12;             // / T_OUT
            v = __ldg(&xs[(bb * T_DIM + i) * D4 + lane]);
        }
        out[(size_t)frame * D4 + lane] = v;
    }
}

// ---------------------------------------------------------------------------
extern "C" void kernel_launch(void* const* d_in, const int* in_sizes, int n_in,
                              void* d_out, int out_size) {
    const float* xs  = (const float*)d_in[0];   // [B, T, D] f32
    const int*   dur = (const int*)d_in[1];     // [B, T] i32
    float* out = (float*)d_out;                 // [B, T_OUT, D] f32
    (void)in_sizes; (void)n_in; (void)out_size;

    prep_kernel<<<B_DIM + 1, T_DIM>>>(dur);

    dim3 blk(D4, 4);                            // 384 threads
    dim3 grd((B_DIM * T_OUT) / 16);             // 8192 blocks
    gather_kernel<<<grd, blk>>>((const float4*)xs, (float4*)out);
}

// round 3
// speedup vs baseline: 1.6141x; 1.1232x over previous
#include <cuda_runtime.h>
#include <stdint.h>

// Problem constants (from reference setup_inputs)
#define B_DIM 32
#define T_DIM 512
#define D_DIM 384
#define DUR_MAX 8
#define T_OUT (T_DIM * DUR_MAX)   // 4096
#define D4 (D_DIM / 4)            // 96 float4 per frame

// Scratch (allocation-free rule: __device__ globals)
__device__ int g_total;
__device__ int g_idx[B_DIM * T_OUT];   // frame -> phoneme index, -1 = pad

// ---------------------------------------------------------------------------
// Fused prep kernel: grid = 33 blocks, 512 threads.
//   block 32     : global duration sum -> g_total
//   blocks 0..31 : per-row shfl scan + scatter idx map (+ all-zero patch)
// Block 32's result is needed by blocks 0..31 ONLY in the all-zero case; we
// handle that by having every row block ALSO check its own row sum: when the
// global total is zero every row sum is zero, so each row block can decide
// locally (row_sum==0 alone is not enough, but we patch conservatively:
// row blocks write the normal map; a second tiny kernel applies the patch
// after g_total is known). To stay one-kernel-cheap, the patch is done by
// the gather grid's first 32 blocks' y==0 warps... Simpler: keep the patch
// in prep via a grid-wide race-free trick: block 32 writes g_total; row
// blocks don't need it. The gather reads g_total (uniform) and patches pad
// frames on the fly -- but branch-free via arithmetic select.
// ---------------------------------------------------------------------------
__global__ void __launch_bounds__(T_DIM) prep_kernel(const int* __restrict__ dur) {
    const int b = blockIdx.x;
    const int j = threadIdx.x;

    if (b == B_DIM) {
        const int4* d4 = (const int4*)dur;          // 4096 int4
        int sum = 0;
        #pragma unroll
        for (int i = 0; i < 8; ++i) {
            int4 v = d4[j + i * T_DIM];
            sum += v.x + v.y + v.z + v.w;
        }
        #pragma unroll
        for (int off = 16; off > 0; off >>= 1)
            sum += __shfl_down_sync(0xffffffffu, sum, off);
        __shared__ int sw[16];
        if ((j & 31) == 0) sw[j >> 5] = sum;
        __syncthreads();
        if (j < 16) {
            int s = sw[j];
            #pragma unroll
            for (int off = 8; off > 0; off >>= 1)
                s += __shfl_down_sync(0xffffu, s, off);
            if (j == 0) g_total = s;
        }
        return;
    }

    // ---- per-row inclusive scan of durations ----
    const int lane = j & 31;
    const int wid  = j >> 5;                        // 16 warps
    int d = dur[b * T_DIM + j];

    int x = d;
    #pragma unroll
    for (int off = 1; off < 32; off <<= 1) {
        int v = __shfl_up_sync(0xffffffffu, x, off);
        if (lane >= off) x += v;
    }

    __shared__ int warpsum[16];
    __shared__ int warppre[16];
    if (lane == 31) warpsum[wid] = x;
    __syncthreads();
    if (j < 16) {
        int v = warpsum[j];
        int p = v;
        #pragma unroll
        for (int off = 1; off < 16; off <<= 1) {
            int t = __shfl_up_sync(0xffffu, p, off);
            if (j >= off) p += t;
        }
        warppre[j] = p - v;                         // exclusive prefix of warp sums
    }
    __syncthreads();

    const int end   = x + warppre[wid];             // inclusive cumsum
    const int start = end - d;
    int* __restrict__ idx = g_idx + b * T_OUT;
    for (int k = start; k < end; ++k) idx[k] = j;

    __shared__ int s_total;
    if (j == T_DIM - 1) s_total = end;
    __syncthreads();
    for (int t = s_total + j; t < T_OUT; t += T_DIM) idx[t] = -1;
}

// ---------------------------------------------------------------------------
// Gather: block (96,4). Each thread owns 8 CONTIGUOUS frames -> idx loads are
// two int4 (LDG.128), then 8 independent gather+store pairs (MLP=8).
// Block covers 32 frames; grid = B*T_OUT/32 = 4096 blocks.
// ---------------------------------------------------------------------------
__global__ void __launch_bounds__(D4 * 4) gather_kernel(
    const float4* __restrict__ xs, float4* __restrict__ out)
{
    const int base  = blockIdx.x * 32 + threadIdx.y * 8;  // first of 8 frames
    const int lane  = threadIdx.x;                        // 0..95
    const int tot   = g_total;

    // 8 indices via two vector loads (g_idx 16B-aligned at base: base % 8 == 0)
    const int4* ip = (const int4*)(g_idx + base);
    int4 i0 = __ldg(ip);
    int4 i1 = __ldg(ip + 1);
    int id[8] = { i0.x, i0.y, i0.z, i0.w, i1.x, i1.y, i1.z, i1.w };

    const int bb   = base >> 12;                          // batch row (/ T_OUT)
    const int tloc = base & (T_OUT - 1);                  // frame within row
    const float4* xrow = xs + bb * (T_DIM * D4) + lane;

    // all-zero edge case: pad frames t<T_DIM become identity map
    if (tot == 0) {
        #pragma unroll
        for (int k = 0; k < 8; ++k)
            if (id[k] < 0 && (tloc + k) < T_DIM) id[k] = tloc + k;
    }

    float4 v[8];
    #pragma unroll
    for (int k = 0; k < 8; ++k) {
        v[k] = make_float4(0.f, 0.f, 0.f, 0.f);
        if (id[k] >= 0) v[k] = __ldg(xrow + id[k] * D4);
    }

    float4* op = out + (size_t)base * D4 + lane;
    #pragma unroll
    for (int k = 0; k < 8; ++k) {
        // streaming store: evict-first in L2, keep xs resident
        asm volatile("st.global.cs.v4.f32 [%0], {%1,%2,%3,%4};"
                     :: "l"(op + k * D4),
                        "f"(v[k].x), "f"(v[k].y), "f"(v[k].z), "f"(v[k].w)
                     : "memory");
    }
}

// ---------------------------------------------------------------------------
extern "C" void kernel_launch(void* const* d_in, const int* in_sizes, int n_in,
                              void* d_out, int out_size) {
    const float* xs  = (const float*)d_in[0];   // [B, T, D] f32
    const int*   dur = (const int*)d_in[1];     // [B, T] i32
    float* out = (float*)d_out;                 // [B, T_OUT, D] f32
    (void)in_sizes; (void)n_in; (void)out_size;

    prep_kernel<<<B_DIM + 1, T_DIM>>>(dur);

    dim3 blk(D4, 4);                            // 384 threads
    dim3 grd((B_DIM * T_OUT) / 32);             // 4096 blocks
    gather_kernel<<<grd, blk>>>((const float4*)xs, (float4*)out);
}